// round 7
// baseline (speedup 1.0000x reference)
#include <cuda_runtime.h>
#include <cstdint>

// InteractingSites: per-frame all-pairs soft-core Coulomb.
// DUAL-FRAME f32x2 packing: lo half = frame A, hi half = frame B. Identical
// pair structure in both halves -> every f32x2 op does one pair per frame.
// j-site delivery by 64-bit warp shuffle (no smem site tables).
//
// CTA = 2 frames = 8 warps x 32. Sites tiled T0..T3 (32 each); lane l holds
// packed sites (A:Tk[l], B:Tk[l]) for k=0..3.
//
// Enumeration per frame (each unordered pair exactly once), split 8 ways:
//  Rectangles: rotation r = 0..31, 6 tile combos (Ta[l], Tb[(l+r)&31]), a<b.
//    Warp w: r in [4w, 4w+4).
//  Triangles: per tile k: (Tk[l], Tk[(l+dd)&31]), dd = 1..15 + dd=16 masked
//    to lanes 0..15.  Warp w: dd in {2w+1, 2w+2} (w=7 gets 15 and 16).
//
// Charge factoring: acc_a += q_j * rsqrt(d2+eps) (packed); row charges applied
// once at the end; the two halves reduce to the two frame energies.

#define EPS2_PACKED 0x358637BD358637BDULL  // (1e-6f, 1e-6f)
#define NEG1_PACKED 0xBF800000BF800000ULL  // (-1.0f, -1.0f)
#define S_SITES 128
#define FULLMASK 0xFFFFFFFFu

using u64 = unsigned long long;

__device__ __forceinline__ u64 pk2(float lo, float hi) {
    u64 r;
    asm("mov.b64 %0, {%1, %2};" : "=l"(r) : "f"(lo), "f"(hi));
    return r;
}
__device__ __forceinline__ void unpk2(u64 v, float& lo, float& hi) {
    asm("mov.b64 {%0, %1}, %2;" : "=f"(lo), "=f"(hi) : "l"(v));
}
__device__ __forceinline__ u64 fma2(u64 a, u64 b, u64 c) {
    u64 d;
    asm("fma.rn.f32x2 %0, %1, %2, %3;" : "=l"(d) : "l"(a), "l"(b), "l"(c));
    return d;
}
__device__ __forceinline__ float frsqrt(float x) {
    float r;
    asm("rsqrt.approx.f32 %0, %1;" : "=f"(r) : "f"(x));
    return r;
}

// acc += jq * rsqrt(|row-j|^2 + eps), elementwise on both packed halves.
__device__ __forceinline__ void grp(u64 rx, u64 ry, u64 rz,
                                    u64 jx, u64 jy, u64 jz, u64 jq,
                                    u64& acc) {
    u64 dx = fma2(jx, (u64)NEG1_PACKED, rx);   // row - j
    u64 dy = fma2(jy, (u64)NEG1_PACKED, ry);
    u64 dz = fma2(jz, (u64)NEG1_PACKED, rz);
    u64 r2 = fma2(dz, dz, (u64)EPS2_PACKED);
    r2 = fma2(dy, dy, r2);
    r2 = fma2(dx, dx, r2);
    float rl, rh;
    unpk2(r2, rl, rh);
    u64 rs = pk2(frsqrt(rl), frsqrt(rh));
    acc = fma2(jq, rs, acc);
}

__device__ __forceinline__ u64 shfl64(u64 v, int src) {
    return (u64)__shfl_sync(FULLMASK, (unsigned long long)v, src);
}

__global__ __launch_bounds__(256, 4)
void interacting_sites_kernel(const float* __restrict__ positions,
                              const float* __restrict__ charges,
                              float* __restrict__ out,
                              int num_frames) {
    __shared__ float warp_sumA[8];
    __shared__ float warp_sumB[8];

    const int w = threadIdx.x >> 5;
    const int l = threadIdx.x & 31;

    const int fidA = blockIdx.x * 2;
    const bool hasB = (fidA + 1) < num_frames;
    const int fidB = hasB ? fidA + 1 : fidA;

    // Lane's packed sites: (A:Tk[l], B:Tk[l])
    const long long baseA = (long long)fidA * S_SITES;
    const long long baseB = (long long)fidB * S_SITES;
    u64 px[4], py[4], pz[4], pq[4];
    float rqA[4], rqB[4];
#pragma unroll
    for (int k = 0; k < 4; ++k) {
        const long long ia = baseA + k * 32 + l;
        const long long ib = baseB + k * 32 + l;
        const float* pa = positions + ia * 3;
        const float* pb = positions + ib * 3;
        px[k] = pk2(pa[0], pb[0]);
        py[k] = pk2(pa[1], pb[1]);
        pz[k] = pk2(pa[2], pb[2]);
        rqA[k] = charges[ia];
        rqB[k] = charges[ib];
        pq[k] = pk2(rqA[k], rqB[k]);
    }

    u64 acc0 = 0ULL, acc1 = 0ULL, acc2 = 0ULL, acc3 = 0ULL;

    // ── Rectangles: warp w handles rotations r in [4w, 4w+4) ──
#pragma unroll
    for (int i = 0; i < 4; ++i) {
        const int src = l + (w << 2) + i;   // shfl wraps mod 32

        const u64 j1x = shfl64(px[1], src), j1y = shfl64(py[1], src),
                  j1z = shfl64(pz[1], src), j1q = shfl64(pq[1], src);
        const u64 j2x = shfl64(px[2], src), j2y = shfl64(py[2], src),
                  j2z = shfl64(pz[2], src), j2q = shfl64(pq[2], src);
        const u64 j3x = shfl64(px[3], src), j3y = shfl64(py[3], src),
                  j3z = shfl64(pz[3], src), j3q = shfl64(pq[3], src);

        grp(px[0], py[0], pz[0], j1x, j1y, j1z, j1q, acc0);
        grp(px[0], py[0], pz[0], j2x, j2y, j2z, j2q, acc0);
        grp(px[0], py[0], pz[0], j3x, j3y, j3z, j3q, acc0);
        grp(px[1], py[1], pz[1], j2x, j2y, j2z, j2q, acc1);
        grp(px[1], py[1], pz[1], j3x, j3y, j3z, j3q, acc1);
        grp(px[2], py[2], pz[2], j3x, j3y, j3z, j3q, acc2);
    }

    // ── Triangles: warp w handles dd in {2w+1, 2w+2}; dd=16 masked l<16 ──
#pragma unroll
    for (int i = 0; i < 2; ++i) {
        const int dd = (w << 1) + 1 + i;    // 1..16 across 8 warps
        const int src = l + dd;

        const u64 t0x = shfl64(px[0], src), t0y = shfl64(py[0], src),
                  t0z = shfl64(pz[0], src), t0q = shfl64(pq[0], src);
        const u64 t1x = shfl64(px[1], src), t1y = shfl64(py[1], src),
                  t1z = shfl64(pz[1], src), t1q = shfl64(pq[1], src);
        const u64 t2x = shfl64(px[2], src), t2y = shfl64(py[2], src),
                  t2z = shfl64(pz[2], src), t2q = shfl64(pq[2], src);
        const u64 t3x = shfl64(px[3], src), t3y = shfl64(py[3], src),
                  t3z = shfl64(pz[3], src), t3q = shfl64(pq[3], src);

        if (dd < 16 || l < 16) {
            grp(px[0], py[0], pz[0], t0x, t0y, t0z, t0q, acc0);
            grp(px[1], py[1], pz[1], t1x, t1y, t1z, t1q, acc1);
            grp(px[2], py[2], pz[2], t2x, t2y, t2z, t2q, acc2);
            grp(px[3], py[3], pz[3], t3x, t3y, t3z, t3q, acc3);
        }
    }

    // Row charges applied once (packed), split halves, reduce
    u64 e = fma2(pq[0], acc0, 0ULL);
    e = fma2(pq[1], acc1, e);
    e = fma2(pq[2], acc2, e);
    e = fma2(pq[3], acc3, e);
    float eA, eB;
    unpk2(e, eA, eB);
#pragma unroll
    for (int o = 16; o > 0; o >>= 1) {
        eA += __shfl_xor_sync(FULLMASK, eA, o);
        eB += __shfl_xor_sync(FULLMASK, eB, o);
    }
    if (l == 0) {
        warp_sumA[w] = eA;
        warp_sumB[w] = eB;
    }
    __syncthreads();
    if (threadIdx.x == 0) {
        float sA = 0.f, sB = 0.f;
#pragma unroll
        for (int k = 0; k < 8; ++k) {
            sA += warp_sumA[k];
            sB += warp_sumB[k];
        }
        out[fidA] = sA;
        if (hasB) out[fidA + 1] = sB;
    }
}

extern "C" void kernel_launch(void* const* d_in, const int* in_sizes, int n_in,
                              void* d_out, int out_size) {
    const float* positions = (const float*)d_in[0];  // [N,3] f32
    const float* charges   = (const float*)d_in[1];  // [N]   f32
    float* out = (float*)d_out;                      // [B]   f32

    const int num_frames = out_size;
    const int grid = (num_frames + 1) / 2;
    interacting_sites_kernel<<<grid, 256>>>(positions, charges, out, num_frames);
}